// round 3
// baseline (speedup 1.0000x reference)
#include <cuda_runtime.h>
#include <cuda_bf16.h>
#include <cstdint>

#define BB 32
#define SS 100
#define TT 100
#define EE 128
#define HH 256
#define VV 32000
#define G3 (3*HH)
#define TV (TT*VV)
#define GRIDN 148
#define BST 36           // padded smem stride (floats): 144B, 16B-aligned, 4-way max conflict

// ---------------- device scratch ----------------
__device__ float g_Xih[BB*SS*G3];
__device__ float g_enc_outs[BB*SS*HH];
__device__ float g_enc_part[BB*SS];
__device__ float g_h[2][BB*HH];
__device__ float g_ctx[BB*HH];
__device__ unsigned long long g_amax[2][BB];
__device__ unsigned g_ctr;
__device__ float g_oWT[(size_t)HH*VV];    // out_W transposed [k][v]
__device__ float g_eWihT[EE*G3];          // enc_Wih transposed [k][row]

// ---------------- helpers ----------------
__device__ __forceinline__ float sigf(float x) { return 1.0f / (1.0f + expf(-x)); }

__device__ __forceinline__ unsigned fkey(float f) {
    unsigned u = __float_as_uint(f);
    return (u & 0x80000000u) ? ~u : (u | 0x80000000u);
}
__device__ __forceinline__ unsigned long long pk2(float x, float y) {
    unsigned long long r;
    asm("mov.b64 %0, {%1, %2};" : "=l"(r) : "f"(x), "f"(y));
    return r;
}
__device__ __forceinline__ void upk2(unsigned long long p, float &x, float &y) {
    asm("mov.b64 {%0, %1}, %2;" : "=f"(x), "=f"(y) : "l"(p));
}
__device__ __forceinline__ unsigned long long fma2(unsigned long long a,
                                                   unsigned long long b,
                                                   unsigned long long c) {
    unsigned long long d;
    asm("fma.rn.f32x2 %0, %1, %2, %3;" : "=l"(d) : "l"(a), "l"(b), "l"(c));
    return d;
}

// grid barrier: monotonic counter, release fence + acquire poll.
__device__ __forceinline__ void gbar(int &nbar) {
    __syncthreads();
    if (threadIdx.x == 0) {
        __threadfence();
        unsigned tgt = (unsigned)(nbar + 1) * GRIDN;
        atomicAdd(&g_ctr, 1u);
        unsigned iter = 0;
        while (true) {
            unsigned v;
            asm volatile("ld.acquire.gpu.global.u32 %0, [%1];" : "=r"(v) : "l"(&g_ctr));
            if (v >= tgt) break;
            if (++iter > 4000000u) break;
            __nanosleep(32);
        }
        __threadfence();
    }
    nbar++;
    __syncthreads();
}

__global__ void k_reset() { g_ctr = 0u; }

__device__ __forceinline__ float rsum256(float v, float* red) {
    int tid = threadIdx.x;
    red[tid] = v; __syncthreads();
    #pragma unroll
    for (int o = 128; o > 0; o >>= 1) { if (tid < o) red[tid] += red[tid + o]; __syncthreads(); }
    float r = red[0]; __syncthreads();
    return r;
}
__device__ __forceinline__ float rmax256(float v, float* red) {
    int tid = threadIdx.x;
    red[tid] = v; __syncthreads();
    #pragma unroll
    for (int o = 128; o > 0; o >>= 1) { if (tid < o) red[tid] = fmaxf(red[tid], red[tid + o]); __syncthreads(); }
    float r = red[0]; __syncthreads();
    return r;
}

// ---------------- the megakernel ----------------
__global__ void __launch_bounds__(256, 1)
mega(const int* __restrict__ ing, const float* __restrict__ emb,
     const float* __restrict__ eWih, const float* __restrict__ eWhh,
     const float* __restrict__ ebih, const float* __restrict__ ebhh,
     const float* __restrict__ dWih, const float* __restrict__ dWhh,
     const float* __restrict__ dbih, const float* __restrict__ dbhh,
     const float* __restrict__ aW, const float* __restrict__ ab,
     const float* __restrict__ oW, const float* __restrict__ ob,
     float* __restrict__ out)
{
    extern __shared__ float dyn[];
    float* wsm = dyn;             // 3840 floats (weights slice)
    float* buf = dyn + 3840;      // 23040 floats: [k][b] staging, stride BST

    __shared__ float S[8][6][32];
    __shared__ float red[256];
    __shared__ float ws[128];
    __shared__ int   toks[BB];
    __shared__ unsigned long long slots[BB];

    const int c = blockIdx.x, tid = threadIdx.x;
    const int w = tid >> 5, lane = tid & 31;
    const int tx = tid & 31, ty = tid >> 5;
    int nbar = 0;

    // ============ Phase A: zero h0, enc-weights->smem, transposes ============
    if (c == 0) for (int i = tid; i < BB*HH; i += 256) g_h[0][i] = 0.0f;
    if (c < 128) {
        for (int i = tid; i < 1536; i += 256) {
            int jlg = i >> 8, k = i & 255;
            int jl = jlg / 3, g = jlg % 3;
            wsm[i] = eWhh[(g*256 + 2*c + jl)*HH + k];
        }
    }
    // tiled transposes: 8000 oW tiles + 96 eWih tiles
    {
        float* tbuf = buf;   // 32x33
        for (int tile = c; tile < 8096; tile += GRIDN) {
            __syncthreads();
            if (tile < 8000) {
                int vt = tile >> 3, kt = tile & 7;
                int v0 = vt*32, k0 = kt*32;
                #pragma unroll
                for (int i = 0; i < 4; i++) {
                    int vv = ty + 8*i;
                    tbuf[vv*33 + tx] = oW[(size_t)(v0+vv)*HH + k0 + tx];
                }
                __syncthreads();
                #pragma unroll
                for (int i = 0; i < 4; i++) {
                    int kk = ty + 8*i;
                    g_oWT[(size_t)(k0+kk)*VV + v0 + tx] = tbuf[tx*33 + kk];
                }
            } else {
                int tt = tile - 8000;
                int rt = tt >> 2, kt = tt & 3;
                int r0 = rt*32, k0 = kt*32;
                #pragma unroll
                for (int i = 0; i < 4; i++) {
                    int rr = ty + 8*i;
                    tbuf[rr*33 + tx] = eWih[(size_t)(r0+rr)*EE + k0 + tx];
                }
                __syncthreads();
                #pragma unroll
                for (int i = 0; i < 4; i++) {
                    int kk = ty + 8*i;
                    g_eWihT[(k0+kk)*G3 + r0 + tx] = tbuf[tx*33 + kk];
                }
            }
        }
    }
    gbar(nbar);

    // ============ Phase B: Xih = emb_src @ eWih^T + bih (coalesced GEMM) ============
    if (c < 100) {
        int p0 = c*32;
        if (tid < 32) toks[tid] = ing[p0 + tid];
        __syncthreads();
        // stage xs[k][p] (stride BST)
        for (int idx = tid; idx < EE*32; idx += 256) {
            int p = idx >> 7, k = idx & 127;
            buf[k*BST + p] = emb[(size_t)toks[p]*EE + k];
        }
        __syncthreads();
        // thread owns rows r = tid, tid+256, tid+512; acc over 32 p as 16 b64
        unsigned long long acc[3][16];
        #pragma unroll
        for (int g = 0; g < 3; g++) {
            float bi = ebih[tid + g*256];
            unsigned long long bv = pk2(bi, bi);
            #pragma unroll
            for (int j = 0; j < 16; j++) acc[g][j] = bv;
        }
        #pragma unroll 2
        for (int k = 0; k < EE; k++) {
            float w0 = g_eWihT[k*G3 + tid];
            float w1 = g_eWihT[k*G3 + 256 + tid];
            float w2 = g_eWihT[k*G3 + 512 + tid];
            unsigned long long W0 = pk2(w0, w0), W1 = pk2(w1, w1), W2 = pk2(w2, w2);
            const ulonglong2* xp = (const ulonglong2*)(buf + k*BST);
            #pragma unroll
            for (int i = 0; i < 8; i++) {
                ulonglong2 hv = xp[i];
                acc[0][2*i]   = fma2(W0, hv.x, acc[0][2*i]);
                acc[0][2*i+1] = fma2(W0, hv.y, acc[0][2*i+1]);
                acc[1][2*i]   = fma2(W1, hv.x, acc[1][2*i]);
                acc[1][2*i+1] = fma2(W1, hv.y, acc[1][2*i+1]);
                acc[2][2*i]   = fma2(W2, hv.x, acc[2][2*i]);
                acc[2][2*i+1] = fma2(W2, hv.y, acc[2][2*i+1]);
            }
        }
        #pragma unroll
        for (int g = 0; g < 3; g++) {
            int r = tid + g*256;
            #pragma unroll
            for (int j = 0; j < 16; j++) {
                float f0, f1;
                upk2(acc[g][j], f0, f1);
                g_Xih[(size_t)(p0 + 2*j)*G3 + r] = f0;
                g_Xih[(size_t)(p0 + 2*j + 1)*G3 + r] = f1;
            }
        }
    }
    gbar(nbar);

    // ============ Encoder: 100 steps ============
    for (int s = 0; s < SS; s++) {
        if (c < 128) {
            const float* hin = g_h[s & 1];
            for (int idx = tid; idx < BB*HH; idx += 256)
                buf[(idx & (HH-1))*BST + (idx >> 8)] = hin[idx];
            __syncthreads();
            float hreg[32];
            #pragma unroll
            for (int kk = 0; kk < 32; kk++) hreg[kk] = buf[(32*w + kk)*BST + lane];
            #pragma unroll
            for (int row = 0; row < 6; row++) {
                const float4* wv = (const float4*)(wsm + row*256 + 32*w);
                float a0=0,a1=0,a2=0,a3=0;
                #pragma unroll
                for (int i = 0; i < 8; i++) {
                    float4 x = wv[i];
                    a0 += x.x*hreg[4*i]; a1 += x.y*hreg[4*i+1];
                    a2 += x.z*hreg[4*i+2]; a3 += x.w*hreg[4*i+3];
                }
                S[w][row][lane] = (a0+a1)+(a2+a3);
            }
            __syncthreads();
            if (w < 2) {
                int j = 2*c + w, b = lane;
                float rs=0, zs=0, ns=0;
                #pragma unroll
                for (int ww = 0; ww < 8; ww++) {
                    rs += S[ww][w*3+0][b]; zs += S[ww][w*3+1][b]; ns += S[ww][w*3+2][b];
                }
                const float* gi = g_Xih + ((size_t)b*SS + s)*G3;
                float r = sigf(gi[j] + rs + ebhh[j]);
                float z = sigf(gi[HH + j] + zs + ebhh[HH + j]);
                float n = tanhf(gi[2*HH + j] + r*(ns + ebhh[2*HH + j]));
                float hprev = buf[j*BST + b];
                float h2 = (1.0f - z)*n + z*hprev;
                g_h[(s+1) & 1][b*HH + j] = h2;
                g_enc_outs[((size_t)b*SS + s)*HH + j] = h2;
            }
        }
        gbar(nbar);
    }

    // ============ enc_part + decoder weight slice ============
    if (c < 128) {
        int j0 = 2*c;
        for (int g = tid; g < 3840; g += 256) {
            int jl = (g >= 1920) ? 1 : 0;
            int gg = g - jl*1920;
            int j = j0 + jl;
            int rl, k;
            if (gg < 640)       { rl = 0; k = gg; }
            else if (gg < 1280) { rl = 1; k = gg - 640; }
            else if (gg < 1664) { rl = 2; k = gg - 1280; }
            else                { rl = 3; k = gg - 1664; }
            float v;
            if (rl == 0)      v = (k < 384) ? dWih[(size_t)j*384 + k]          : dWhh[(size_t)j*HH + (k-384)];
            else if (rl == 1) v = (k < 384) ? dWih[(size_t)(256+j)*384 + k]    : dWhh[(size_t)(256+j)*HH + (k-384)];
            else if (rl == 2) v = dWih[(size_t)(512+j)*384 + k];
            else              v = dWhh[(size_t)(512+j)*HH + k];
            wsm[g] = v;
        }
    }
    {
        int gt = c*256 + tid;
        if (gt < BB*SS) {
            const float4* e4 = (const float4*)(g_enc_outs + (size_t)gt*HH);
            const float4* w4 = (const float4*)aW;
            float a0 = ab[0], a1=0,a2=0,a3=0;
            #pragma unroll 8
            for (int k = 0; k < HH/4; k++) {
                float4 e = e4[k]; float4 ww = __ldg(&w4[k]);
                a0 += e.x*ww.x; a1 += e.y*ww.y; a2 += e.z*ww.z; a3 += e.w*ww.w;
            }
            g_enc_part[gt] = (a0+a1)+(a2+a3);
        }
    }
    gbar(nbar);

    // ============ decoder ============
    static const int rowoff_[8] = {0,640,1280,1664,1920,2560,3200,3584};
    static const int s0row_[8] = {0,0,1,2,4,4,5,6};
    static const int s0k_[8]   = {0,480,320,160,0,480,320,160};
    static const int s0len_[8] = {480,160,320,224,480,160,320,224};
    static const int s1row_[8] = {0,1,2,3,4,5,6,7};
    static const int s1len_[8] = {0,320,160,256,0,320,160,256};

    auto do_attn = [&](const float* h) {
        int i = c - 125;
        int nb = (i + 23 < BB) ? 2 : 1;
        for (int q = 0; q < nb; q++) {
            int b = i + q*23;
            float p = h[b*HH + tid] * aW[HH + tid];
            float hw = rsum256(p, red);
            float sc = (tid < SS) ? (g_enc_part[b*SS + tid] + hw) : -1e30f;
            float mx = rmax256(sc, red);
            float e = (tid < SS) ? expf(sc - mx) : 0.0f;
            if (tid < 128) ws[tid] = (tid < SS) ? e : 0.0f;
            float inv = 1.0f / rsum256(e, red);
            __syncthreads();
            int j = tid;
            const float* eo = g_enc_outs + (size_t)b*SS*HH + j;
            float a0=0, a1=0;
            #pragma unroll 4
            for (int s = 0; s < SS; s += 2) {
                a0 += ws[s] * eo[(size_t)s*HH];
                a1 += ws[s+1] * eo[(size_t)(s+1)*HH];
            }
            g_ctx[b*HH + j] = (a0 + a1) * inv;
            __syncthreads();
        }
    };

    if (c >= 125) do_attn(g_h[0]);
    gbar(nbar);

    for (int t = 0; t < TT; t++) {
        // -------- P1: GRU --------
        if (c < 128) {
            if (tid < BB)
                toks[tid] = (t == 0) ? 1
                    : (int)(0xFFFFFFFFu - (unsigned)(g_amax[(t-1) & 1][tid] & 0xFFFFFFFFull));
            if (c == 0 && tid >= 32 && tid < 64) g_amax[t & 1][tid - 32] = 0ULL;
            __syncthreads();
            const float* hin = g_h[t & 1];
            #pragma unroll
            for (int i = 0; i < 20; i++) {
                int k4 = w*20 + i, k = 4*k4;
                float4 v;
                if (k4 < 32)       v = *(const float4*)(emb + (size_t)toks[lane]*EE + k);
                else if (k4 < 96)  v = *(const float4*)(g_ctx + lane*HH + (k - 128));
                else               v = *(const float4*)(hin + lane*HH + (k - 384));
                buf[(k+0)*BST+lane]=v.x; buf[(k+1)*BST+lane]=v.y;
                buf[(k+2)*BST+lane]=v.z; buf[(k+3)*BST+lane]=v.w;
            }
            __syncthreads();
            {
                int r0 = s0row_[w], k0 = s0k_[w], l0 = s0len_[w];
                const float4* wv = (const float4*)(wsm + rowoff_[r0] + k0);
                int bo = (((r0 & 3) == 3) ? 384 : 0) + k0;
                float a0=0,a1=0,a2=0,a3=0;
                #pragma unroll 4
                for (int i = 0; i < l0/4; i++) {
                    float4 x = wv[i];
                    int kb = (bo + 4*i)*BST + lane;
                    a0 += x.x*buf[kb]; a1 += x.y*buf[kb+BST];
                    a2 += x.z*buf[kb+2*BST]; a3 += x.w*buf[kb+3*BST];
                }
                S[w][0][lane] = (a0+a1)+(a2+a3);
            }
            {
                int r1 = s1row_[w], l1 = s1len_[w];
                float acc = 0.0f;
                if (l1 > 0) {
                    const float4* wv = (const float4*)(wsm + rowoff_[r1]);
                    int bo = ((r1 & 3) == 3) ? 384 : 0;
                    float a0=0,a1=0,a2=0,a3=0;
                    #pragma unroll 4
                    for (int i = 0; i < l1/4; i++) {
                        float4 x = wv[i];
                        int kb = (bo + 4*i)*BST + lane;
                        a0 += x.x*buf[kb]; a1 += x.y*buf[kb+BST];
                        a2 += x.z*buf[kb+2*BST]; a3 += x.w*buf[kb+3*BST];
                    }
                    acc = (a0+a1)+(a2+a3);
                }
                S[w][1][lane] = acc;
            }
            __syncthreads();
            if (w == 0 || w == 4) {
                int jl = w >> 2, base = jl*4;
                int j = 2*c + jl, b = lane;
                float r_in = S[base+0][0][b] + S[base+1][0][b];
                float z_in = S[base+1][1][b] + S[base+2][0][b];
                float nx   = S[base+2][1][b] + S[base+3][0][b];
                float nh   = S[base+3][1][b];
                float r = sigf(r_in + dbih[j] + dbhh[j]);
                float z = sigf(z_in + dbih[HH + j] + dbhh[HH + j]);
                float n = tanhf(nx + dbih[2*HH + j] + r*(nh + dbhh[2*HH + j]));
                float hprev = buf[(384 + j)*BST + b];
                float h2 = (1.0f - z)*n + z*hprev;
                g_h[(t+1) & 1][b*HH + j] = h2;
            }
        }
        gbar(nbar);

        // -------- P2: logits+argmax (c<125) || attn t+1 (c>=125) --------
        if (c < 125) {
            const float* h = g_h[(t+1) & 1];
            if (tid < BB) slots[tid] = 0ULL;
            for (int idx = tid; idx < BB*HH; idx += 256)
                buf[(idx & (HH-1))*BST + (idx >> 8)] = h[idx];
            __syncthreads();

            if (tid < 128) {
                int v0 = c*256 + 2*tid;
                float2 b2 = *(const float2*)(ob + v0);
                unsigned long long acc0[16], acc1[16];
                unsigned long long bi0 = pk2(b2.x, b2.x), bi1 = pk2(b2.y, b2.y);
                #pragma unroll
                for (int i = 0; i < 16; i++) { acc0[i] = bi0; acc1[i] = bi1; }

                const float* wt = g_oWT + v0;
                #pragma unroll 2
                for (int k = 0; k < HH; k++) {
                    float2 w2 = *(const float2*)(wt + (size_t)k*VV);
                    unsigned long long W0 = pk2(w2.x, w2.x);
                    unsigned long long W1 = pk2(w2.y, w2.y);
                    const ulonglong2* hp = (const ulonglong2*)(buf + k*BST);
                    #pragma unroll
                    for (int i = 0; i < 8; i++) {
                        ulonglong2 hv = hp[i];
                        acc0[2*i]   = fma2(W0, hv.x, acc0[2*i]);
                        acc0[2*i+1] = fma2(W0, hv.y, acc0[2*i+1]);
                        acc1[2*i]   = fma2(W1, hv.x, acc1[2*i]);
                        acc1[2*i+1] = fma2(W1, hv.y, acc1[2*i+1]);
                    }
                }
                float* outp = out + (size_t)t*VV;
                #pragma unroll
                for (int j = 0; j < 16; j++) {
                    float x0, x1, y0, y1;
                    upk2(acc0[j], x0, x1);   // row v0:   b=2j -> x0, b=2j+1 -> x1
                    upk2(acc1[j], y0, y1);   // row v0+1: b=2j -> y0, b=2j+1 -> y1
                    *(float2*)(outp + (size_t)(2*j)*TV + v0)   = make_float2(x0, y0);
                    *(float2*)(outp + (size_t)(2*j+1)*TV + v0) = make_float2(x1, y1);
                    {
                        unsigned k0 = fkey(x0), k1 = fkey(y0);
                        unsigned key; unsigned vv;
                        if (k1 > k0) { key = k1; vv = (unsigned)(v0+1); } else { key = k0; vv = (unsigned)v0; }
                        unsigned wmax = __reduce_max_sync(0xffffffffu, key);
                        unsigned mask = __ballot_sync(0xffffffffu, key == wmax);
                        if (lane == (__ffs(mask) - 1))
                            atomicMax(&slots[2*j], ((unsigned long long)wmax << 32)
                                                   | (unsigned long long)(0xFFFFFFFFu - vv));
                    }
                    {
                        unsigned k0 = fkey(x1), k1 = fkey(y1);
                        unsigned key; unsigned vv;
                        if (k1 > k0) { key = k1; vv = (unsigned)(v0+1); } else { key = k0; vv = (unsigned)v0; }
                        unsigned wmax = __reduce_max_sync(0xffffffffu, key);
                        unsigned mask = __ballot_sync(0xffffffffu, key == wmax);
                        if (lane == (__ffs(mask) - 1))
                            atomicMax(&slots[2*j+1], ((unsigned long long)wmax << 32)
                                                     | (unsigned long long)(0xFFFFFFFFu - vv));
                    }
                }
            }
            __syncthreads();
            if (tid < BB) atomicMax(&g_amax[t & 1][tid], slots[tid]);
        } else if (t < TT-1) {
            do_attn(g_h[(t+1) & 1]);
        }
        gbar(nbar);
    }
}

// ---------------- host launch ----------------
extern "C" void kernel_launch(void* const* d_in, const int* in_sizes, int n_in,
                              void* d_out, int out_size) {
    const int*   ing      = (const int*)d_in[0];
    const float* emb      = (const float*)d_in[1];
    const float* enc_Wih  = (const float*)d_in[2];
    const float* enc_Whh  = (const float*)d_in[3];
    const float* enc_bih  = (const float*)d_in[4];
    const float* enc_bhh  = (const float*)d_in[5];
    const float* dec_Wih  = (const float*)d_in[6];
    const float* dec_Whh  = (const float*)d_in[7];
    const float* dec_bih  = (const float*)d_in[8];
    const float* dec_bhh  = (const float*)d_in[9];
    const float* attn_W   = (const float*)d_in[10];
    const float* attn_b   = (const float*)d_in[11];
    const float* out_W    = (const float*)d_in[12];
    const float* out_b    = (const float*)d_in[13];
    float* out = (float*)d_out;

    static int configured = 0;
    if (!configured) {
        cudaFuncSetAttribute(mega, cudaFuncAttributeMaxDynamicSharedMemorySize, 110592);
        configured = 1;
    }
    k_reset<<<1, 1>>>();
    mega<<<GRIDN, 256, 107520>>>(ing, emb, enc_Wih, enc_Whh, enc_bih, enc_bhh,
                                 dec_Wih, dec_Whh, dec_bih, dec_bhh,
                                 attn_W, attn_b, out_W, out_b, out);
}

// round 4
// speedup vs baseline: 1.5271x; 1.5271x over previous
#include <cuda_runtime.h>
#include <cuda_bf16.h>
#include <cstdint>

#define BB 32
#define SS 100
#define TT 100
#define EE 128
#define HH 256
#define VV 32000
#define G3 (3*HH)
#define TV (TT*VV)
#define GRIDN 148
#define BST 36      // logits h staging stride [k][b]
#define XST 649     // P1 x staging stride [b][k], gcd(9,32)=1 -> conflict-free
#define EST 193     // encoder weight smem stride [k][col], conflict-free

typedef unsigned long long ull;

// ---------------- device scratch ----------------
__device__ float g_Xih[BB*SS*G3];
__device__ float g_enc_outs[BB*SS*HH];
__device__ float g_enc_part[BB*SS];
__device__ float g_h[2][BB*HH];
__device__ float g_hx[BB*HH];            // encoder h exchange
__device__ float g_ctx[BB*HH];
__device__ ull g_amax[2][BB];
__device__ unsigned g_ctr;
__device__ unsigned g_ectr[BB];          // per-batch-group mini barrier
__device__ float g_oWT[(size_t)HH*VV];   // out_W transposed [k][v]
__device__ float g_eWihT[EE*G3];         // enc_Wih transposed [k][row]

// ---------------- helpers ----------------
__device__ __forceinline__ float sigf(float x) { return 1.0f / (1.0f + expf(-x)); }
__device__ __forceinline__ unsigned fkey(float f) {
    unsigned u = __float_as_uint(f);
    return (u & 0x80000000u) ? ~u : (u | 0x80000000u);
}
__device__ __forceinline__ ull pk2(float x, float y) {
    ull r; asm("mov.b64 %0, {%1, %2};" : "=l"(r) : "f"(x), "f"(y)); return r;
}
__device__ __forceinline__ void upk2(ull p, float &x, float &y) {
    asm("mov.b64 {%0, %1}, %2;" : "=f"(x), "=f"(y) : "l"(p));
}
__device__ __forceinline__ ull fma2(ull a, ull b, ull c) {
    ull d; asm("fma.rn.f32x2 %0, %1, %2, %3;" : "=l"(d) : "l"(a), "l"(b), "l"(c)); return d;
}

// grid barrier (monotonic counter)
__device__ __forceinline__ void gbar(int &nbar) {
    __syncthreads();
    if (threadIdx.x == 0) {
        __threadfence();
        unsigned tgt = (unsigned)(nbar + 1) * GRIDN;
        atomicAdd(&g_ctr, 1u);
        unsigned iter = 0;
        while (true) {
            unsigned v;
            asm volatile("ld.acquire.gpu.global.u32 %0, [%1];" : "=r"(v) : "l"(&g_ctr));
            if (v >= tgt) break;
            if (++iter > 8000000u) break;
            __nanosleep(64);
        }
        __threadfence();
    }
    nbar++;
    __syncthreads();
}

// 4-CTA mini barrier (encoder group), tight poll
__device__ __forceinline__ void minibar(int grp, int step) {
    __syncthreads();
    if (threadIdx.x == 0) {
        __threadfence();
        unsigned tgt = (unsigned)(step + 1) * 4u;
        atomicAdd(&g_ectr[grp], 1u);
        unsigned iter = 0;
        while (true) {
            unsigned v;
            asm volatile("ld.acquire.gpu.global.u32 %0, [%1];" : "=r"(v) : "l"(&g_ectr[grp]));
            if (v >= tgt) break;
            if (++iter > 20000000u) break;
        }
        __threadfence();
    }
    __syncthreads();
}

__global__ void k_reset() {
    g_ctr = 0u;
    for (int i = 0; i < BB; i++) g_ectr[i] = 0u;
}

__device__ __forceinline__ float rsum256(float v, float* red) {
    int tid = threadIdx.x;
    red[tid] = v; __syncthreads();
    #pragma unroll
    for (int o = 128; o > 0; o >>= 1) { if (tid < o) red[tid] += red[tid + o]; __syncthreads(); }
    float r = red[0]; __syncthreads();
    return r;
}
__device__ __forceinline__ float rmax256(float v, float* red) {
    int tid = threadIdx.x;
    red[tid] = v; __syncthreads();
    #pragma unroll
    for (int o = 128; o > 0; o >>= 1) { if (tid < o) red[tid] = fmaxf(red[tid], red[tid + o]); __syncthreads(); }
    float r = red[0]; __syncthreads();
    return r;
}

// ---------------- the megakernel ----------------
__global__ void __launch_bounds__(256, 1)
mega(const int* __restrict__ ing, const float* __restrict__ emb,
     const float* __restrict__ eWih, const float* __restrict__ eWhh,
     const float* __restrict__ ebih, const float* __restrict__ ebhh,
     const float* __restrict__ dWih, const float* __restrict__ dWhh,
     const float* __restrict__ dbih, const float* __restrict__ dbhh,
     const float* __restrict__ aW, const float* __restrict__ ab,
     const float* __restrict__ oW, const float* __restrict__ ob,
     float* __restrict__ out)
{
    extern __shared__ float dyn[];
    float* wsm = dyn;            // decoder: 3840-float weight slice / encoder: wTs[256][EST]
    float* buf = dyn + 3840;     // staging

    __shared__ float S[8][2][32];
    __shared__ float S4[4][3][64];
    __shared__ float hs[HH];
    __shared__ float ebs[192];
    __shared__ float red[256];
    __shared__ float ws[128];
    __shared__ int   toks[BB];
    __shared__ ull   slots[BB];

    const int c = blockIdx.x, tid = threadIdx.x;
    const int w = tid >> 5, lane = tid & 31;
    const int tx = tid & 31, ty = tid >> 5;
    int nbar = 0;

    // ============ Phase A: zero h0 + transposes (oW, eWih) ============
    if (c == 0) for (int i = tid; i < BB*HH; i += 256) g_h[0][i] = 0.0f;
    {
        float* tbuf = buf;   // 32x33
        for (int tile = c; tile < 8096; tile += GRIDN) {
            __syncthreads();
            if (tile < 8000) {
                int vt = tile >> 3, kt = tile & 7;
                int v0 = vt*32, k0 = kt*32;
                #pragma unroll
                for (int i = 0; i < 4; i++) {
                    int vv = ty + 8*i;
                    tbuf[vv*33 + tx] = oW[(size_t)(v0+vv)*HH + k0 + tx];
                }
                __syncthreads();
                #pragma unroll
                for (int i = 0; i < 4; i++) {
                    int kk = ty + 8*i;
                    g_oWT[(size_t)(k0+kk)*VV + v0 + tx] = tbuf[tx*33 + kk];
                }
            } else {
                int tt = tile - 8000;
                int rt = tt >> 2, kt = tt & 3;
                int r0 = rt*32, k0 = kt*32;
                #pragma unroll
                for (int i = 0; i < 4; i++) {
                    int rr = ty + 8*i;
                    tbuf[rr*33 + tx] = eWih[(size_t)(r0+rr)*EE + k0 + tx];
                }
                __syncthreads();
                #pragma unroll
                for (int i = 0; i < 4; i++) {
                    int kk = ty + 8*i;
                    g_eWihT[(k0+kk)*G3 + r0 + tx] = tbuf[tx*33 + kk];
                }
            }
        }
    }
    gbar(nbar);

    // ============ Phase B: Xih GEMM (c<100), then encoder weight slice (c<128) ============
    if (c < 100) {
        int p0 = c*32;
        if (tid < 32) toks[tid] = ing[p0 + tid];
        __syncthreads();
        for (int idx = tid; idx < EE*32; idx += 256) {
            int p = idx >> 7, k = idx & 127;
            buf[k*BST + p] = emb[(size_t)toks[p]*EE + k];
        }
        __syncthreads();
        ull acc[3][16];
        #pragma unroll
        for (int g = 0; g < 3; g++) {
            float bi = ebih[tid + g*256];
            ull bv = pk2(bi, bi);
            #pragma unroll
            for (int j = 0; j < 16; j++) acc[g][j] = bv;
        }
        #pragma unroll 2
        for (int k = 0; k < EE; k++) {
            float w0 = g_eWihT[k*G3 + tid];
            float w1 = g_eWihT[k*G3 + 256 + tid];
            float w2 = g_eWihT[k*G3 + 512 + tid];
            ull W0 = pk2(w0, w0), W1 = pk2(w1, w1), W2 = pk2(w2, w2);
            const ulonglong2* xp = (const ulonglong2*)(buf + k*BST);
            #pragma unroll
            for (int i = 0; i < 8; i++) {
                ulonglong2 hv = xp[i];
                acc[0][2*i]   = fma2(W0, hv.x, acc[0][2*i]);
                acc[0][2*i+1] = fma2(W0, hv.y, acc[0][2*i+1]);
                acc[1][2*i]   = fma2(W1, hv.x, acc[1][2*i]);
                acc[1][2*i+1] = fma2(W1, hv.y, acc[1][2*i+1]);
                acc[2][2*i]   = fma2(W2, hv.x, acc[2][2*i]);
                acc[2][2*i+1] = fma2(W2, hv.y, acc[2][2*i+1]);
            }
        }
        #pragma unroll
        for (int g = 0; g < 3; g++) {
            int r = tid + g*256;
            #pragma unroll
            for (int j = 0; j < 16; j++) {
                float f0, f1;
                upk2(acc[g][j], f0, f1);
                g_Xih[(size_t)(p0 + 2*j)*G3 + r] = f0;
                g_Xih[(size_t)(p0 + 2*j + 1)*G3 + r] = f1;
            }
        }
    }
    __syncthreads();
    if (c < 128) {
        // encoder weights: wTs[k*EST + col], col = g*64+jl, weight row = g*256 + part*64 + jl
        int part = c & 3;
        for (int idx = tid; idx < 192*64; idx += 256) {
            int k4 = idx & 63, r = idx >> 6;
            int g = r >> 6, jl = r & 63;
            float4 v = *(const float4*)(eWhh + (size_t)(g*256 + part*64 + jl)*HH + 4*k4);
            wsm[(4*k4+0)*EST + r] = v.x;
            wsm[(4*k4+1)*EST + r] = v.y;
            wsm[(4*k4+2)*EST + r] = v.z;
            wsm[(4*k4+3)*EST + r] = v.w;
        }
        // bias slice
        for (int i = tid; i < 192; i += 256) {
            int g = i >> 6, jl = i & 63;
            ebs[i] = ebhh[g*256 + part*64 + jl];
        }
        if (tid < HH) hs[tid] = 0.0f;
    }
    gbar(nbar);

    // ============ Encoder: 32 groups x 4 CTAs, mini-barriers only ============
    if (c < 128) {
        int b = c >> 2, part = c & 3;
        for (int s = 0; s < SS; s++) {
            // partials: thread (jl, q)
            int jl = tid & 63, q = tid >> 6;
            float aR = 0.f, aZ = 0.f, aN = 0.f;
            const float* wp = wsm + (q*64)*EST;
            #pragma unroll 4
            for (int kk = 0; kk < 64; kk++) {
                float hv = hs[q*64 + kk];
                aR += wp[kk*EST + jl] * hv;
                aZ += wp[kk*EST + 64 + jl] * hv;
                aN += wp[kk*EST + 128 + jl] * hv;
            }
            S4[q][0][jl] = aR; S4[q][1][jl] = aZ; S4[q][2][jl] = aN;
            __syncthreads();
            if (tid < 64) {
                int j = part*64 + tid;
                float rs = S4[0][0][tid]+S4[1][0][tid]+S4[2][0][tid]+S4[3][0][tid];
                float zs = S4[0][1][tid]+S4[1][1][tid]+S4[2][1][tid]+S4[3][1][tid];
                float ns = S4[0][2][tid]+S4[1][2][tid]+S4[2][2][tid]+S4[3][2][tid];
                const float* gi = g_Xih + ((size_t)b*SS + s)*G3;
                float r = sigf(gi[j] + rs + ebs[tid]);
                float z = sigf(gi[HH + j] + zs + ebs[64 + tid]);
                float n = tanhf(gi[2*HH + j] + r*(ns + ebs[128 + tid]));
                float h2 = (1.0f - z)*n + z*hs[j];
                g_enc_outs[((size_t)b*SS + s)*HH + j] = h2;
                g_hx[b*HH + j] = h2;
                if (s == SS-1) g_h[0][b*HH + j] = h2;
            }
            minibar(b, s);
            if (tid < HH) hs[tid] = g_hx[b*HH + tid];
            __syncthreads();
        }
    }
    gbar(nbar);

    // ============ enc_part + decoder weight slice ============
    if (c < 128) {
        int j0 = 2*c;
        for (int g = tid; g < 3840; g += 256) {
            int jl = (g >= 1920) ? 1 : 0;
            int gg = g - jl*1920;
            int j = j0 + jl;
            int rl, k;
            if (gg < 640)       { rl = 0; k = gg; }
            else if (gg < 1280) { rl = 1; k = gg - 640; }
            else if (gg < 1664) { rl = 2; k = gg - 1280; }
            else                { rl = 3; k = gg - 1664; }
            float v;
            if (rl == 0)      v = (k < 384) ? dWih[(size_t)j*384 + k]          : dWhh[(size_t)j*HH + (k-384)];
            else if (rl == 1) v = (k < 384) ? dWih[(size_t)(256+j)*384 + k]    : dWhh[(size_t)(256+j)*HH + (k-384)];
            else if (rl == 2) v = dWih[(size_t)(512+j)*384 + k];
            else              v = dWhh[(size_t)(512+j)*HH + k];
            wsm[g] = v;
        }
    }
    {
        int gt = c*256 + tid;
        if (gt < BB*SS) {
            const float4* e4 = (const float4*)(g_enc_outs + (size_t)gt*HH);
            const float4* w4 = (const float4*)aW;
            float a0 = ab[0], a1=0,a2=0,a3=0;
            #pragma unroll 8
            for (int k = 0; k < HH/4; k++) {
                float4 e = e4[k]; float4 ww = __ldg(&w4[k]);
                a0 += e.x*ww.x; a1 += e.y*ww.y; a2 += e.z*ww.z; a3 += e.w*ww.w;
            }
            g_enc_part[gt] = (a0+a1)+(a2+a3);
        }
    }
    gbar(nbar);

    // ============ decoder ============
    static const int rowoff_[8] = {0,640,1280,1664,1920,2560,3200,3584};
    static const int s0row_[8] = {0,0,1,2,4,4,5,6};
    static const int s0k_[8]   = {0,480,320,160,0,480,320,160};
    static const int s0len_[8] = {480,160,320,224,480,160,320,224};
    static const int s1row_[8] = {0,1,2,3,4,5,6,7};
    static const int s1len_[8] = {0,320,160,256,0,320,160,256};

    auto do_attn = [&](const float* h) {
        int i = c - 125;
        int nb = (i + 23 < BB) ? 2 : 1;
        for (int q = 0; q < nb; q++) {
            int b = i + q*23;
            float p = h[b*HH + tid] * aW[HH + tid];
            float hw = rsum256(p, red);
            float sc = (tid < SS) ? (g_enc_part[b*SS + tid] + hw) : -1e30f;
            float mx = rmax256(sc, red);
            float e = (tid < SS) ? expf(sc - mx) : 0.0f;
            if (tid < 128) ws[tid] = (tid < SS) ? e : 0.0f;
            float inv = 1.0f / rsum256(e, red);
            __syncthreads();
            int j = tid;
            const float* eo = g_enc_outs + (size_t)b*SS*HH + j;
            float a0=0, a1=0;
            #pragma unroll 4
            for (int s = 0; s < SS; s += 2) {
                a0 += ws[s] * eo[(size_t)s*HH];
                a1 += ws[s+1] * eo[(size_t)(s+1)*HH];
            }
            g_ctx[b*HH + j] = (a0 + a1) * inv;
            __syncthreads();
        }
    };

    if (c >= 125) do_attn(g_h[0]);
    gbar(nbar);

    for (int t = 0; t < TT; t++) {
        // -------- P1: GRU (c<128) --------
        if (c < 128) {
            if (tid < BB)
                toks[tid] = (t == 0) ? 1
                    : (int)(0xFFFFFFFFu - (unsigned)(g_amax[(t-1) & 1][tid] & 0xFFFFFFFFull));
            if (c == 0 && tid >= 32 && tid < 64) g_amax[t & 1][tid - 32] = 0ULL;
            __syncthreads();
            const float* hin = g_h[t & 1];
            // stage x = [emb, ctx, h] as [b][XST], coalesced loads, conflict-free stores
            {
                int b = tid >> 3, f = tid & 7;
                float* xr = buf + b*XST;
                #pragma unroll
                for (int i = 0; i < 4; i++) {
                    int k4 = f + 8*i;
                    float4 v = *(const float4*)(emb + (size_t)toks[b]*EE + 4*k4);
                    xr[4*k4+0]=v.x; xr[4*k4+1]=v.y; xr[4*k4+2]=v.z; xr[4*k4+3]=v.w;
                }
                #pragma unroll
                for (int i = 0; i < 8; i++) {
                    int k4 = f + 8*i;
                    float4 v = *(const float4*)(g_ctx + b*HH + 4*k4);
                    int o = 128 + 4*k4;
                    xr[o]=v.x; xr[o+1]=v.y; xr[o+2]=v.z; xr[o+3]=v.w;
                }
                #pragma unroll
                for (int i = 0; i < 8; i++) {
                    int k4 = f + 8*i;
                    float4 v = *(const float4*)(hin + b*HH + 4*k4);
                    int o = 384 + 4*k4;
                    xr[o]=v.x; xr[o+1]=v.y; xr[o+2]=v.z; xr[o+3]=v.w;
                }
            }
            __syncthreads();
            const float* xb = buf + lane*XST;
            {
                int r0 = s0row_[w], k0 = s0k_[w], l0 = s0len_[w];
                const float4* wv = (const float4*)(wsm + rowoff_[r0] + k0);
                int bo = (((r0 & 3) == 3) ? 384 : 0) + k0;
                float a0=0,a1=0,a2=0,a3=0;
                #pragma unroll 4
                for (int i = 0; i < l0/4; i++) {
                    float4 x = wv[i];
                    const float* xp = xb + bo + 4*i;
                    a0 += x.x*xp[0]; a1 += x.y*xp[1];
                    a2 += x.z*xp[2]; a3 += x.w*xp[3];
                }
                S[w][0][lane] = (a0+a1)+(a2+a3);
            }
            {
                int r1 = s1row_[w], l1 = s1len_[w];
                float acc = 0.0f;
                if (l1 > 0) {
                    const float4* wv = (const float4*)(wsm + rowoff_[r1]);
                    int bo = ((r1 & 3) == 3) ? 384 : 0;
                    float a0=0,a1=0,a2=0,a3=0;
                    #pragma unroll 4
                    for (int i = 0; i < l1/4; i++) {
                        float4 x = wv[i];
                        const float* xp = xb + bo + 4*i;
                        a0 += x.x*xp[0]; a1 += x.y*xp[1];
                        a2 += x.z*xp[2]; a3 += x.w*xp[3];
                    }
                    acc = (a0+a1)+(a2+a3);
                }
                S[w][1][lane] = acc;
            }
            __syncthreads();
            if (w == 0 || w == 4) {
                int jl = w >> 2, base = jl*4;
                int j = 2*c + jl, b = lane;
                float r_in = S[base+0][0][b] + S[base+1][0][b];
                float z_in = S[base+1][1][b] + S[base+2][0][b];
                float nx   = S[base+2][1][b] + S[base+3][0][b];
                float nh   = S[base+3][1][b];
                float r = sigf(r_in + dbih[j] + dbhh[j]);
                float z = sigf(z_in + dbih[HH + j] + dbhh[HH + j]);
                float n = tanhf(nx + dbih[2*HH + j] + r*(nh + dbhh[2*HH + j]));
                float hprev = buf[b*XST + 384 + j];
                float h2 = (1.0f - z)*n + z*hprev;
                g_h[(t+1) & 1][b*HH + j] = h2;
            }
        }
        gbar(nbar);

        // -------- P2: logits+argmax (c<125) || attn t+1 (c>=125) --------
        if (c < 125) {
            const float* h = g_h[(t+1) & 1];
            if (tid < BB) slots[tid] = 0ULL;
            for (int idx = tid; idx < BB*HH; idx += 256)
                buf[(idx & (HH-1))*BST + (idx >> 8)] = h[idx];
            __syncthreads();

            int v = c*256 + tid;
            float bias = ob[v];
            ull acc[16];
            ull binit = pk2(bias, bias);
            #pragma unroll
            for (int i = 0; i < 16; i++) acc[i] = binit;

            const float* wp = g_oWT + v;
            float wreg[8];
            #pragma unroll
            for (int i = 0; i < 8; i++) wreg[i] = wp[(size_t)i*VV];

            for (int k8 = 0; k8 < 32; k8++) {
                float wnext[8];
                if (k8 < 31) {
                    #pragma unroll
                    for (int i = 0; i < 8; i++) wnext[i] = wp[(size_t)(k8*8 + 8 + i)*VV];
                }
                #pragma unroll
                for (int i = 0; i < 8; i++) {
                    int k = k8*8 + i;
                    ull W = pk2(wreg[i], wreg[i]);
                    const ulonglong2* hp = (const ulonglong2*)(buf + k*BST);
                    #pragma unroll
                    for (int jj = 0; jj < 8; jj++) {
                        ulonglong2 hv = hp[jj];
                        acc[2*jj]   = fma2(W, hv.x, acc[2*jj]);
                        acc[2*jj+1] = fma2(W, hv.y, acc[2*jj+1]);
                    }
                }
                if (k8 < 31) {
                    #pragma unroll
                    for (int i = 0; i < 8; i++) wreg[i] = wnext[i];
                }
            }

            float* outp = out + (size_t)t*VV;
            #pragma unroll
            for (int m = 0; m < 16; m++) {
                float f0, f1;
                upk2(acc[m], f0, f1);
                outp[(size_t)(2*m)*TV + v]   = f0;
                outp[(size_t)(2*m+1)*TV + v] = f1;
                {
                    unsigned key = fkey(f0);
                    unsigned wm = __reduce_max_sync(0xffffffffu, key);
                    unsigned mk = __ballot_sync(0xffffffffu, key == wm);
                    if (lane == (__ffs(mk) - 1))
                        atomicMax(&slots[2*m], ((ull)wm << 32) | (ull)(0xFFFFFFFFu - (unsigned)v));
                }
                {
                    unsigned key = fkey(f1);
                    unsigned wm = __reduce_max_sync(0xffffffffu, key);
                    unsigned mk = __ballot_sync(0xffffffffu, key == wm);
                    if (lane == (__ffs(mk) - 1))
                        atomicMax(&slots[2*m+1], ((ull)wm << 32) | (ull)(0xFFFFFFFFu - (unsigned)v));
                }
            }
            __syncthreads();
            if (tid < BB) atomicMax(&g_amax[t & 1][tid], slots[tid]);
        } else if (t < TT-1) {
            do_attn(g_h[(t+1) & 1]);
        }
        gbar(nbar);
    }
}

// ---------------- host launch ----------------
extern "C" void kernel_launch(void* const* d_in, const int* in_sizes, int n_in,
                              void* d_out, int out_size) {
    const int*   ing      = (const int*)d_in[0];
    const float* emb      = (const float*)d_in[1];
    const float* enc_Wih  = (const float*)d_in[2];
    const float* enc_Whh  = (const float*)d_in[3];
    const float* enc_bih  = (const float*)d_in[4];
    const float* enc_bhh  = (const float*)d_in[5];
    const float* dec_Wih  = (const float*)d_in[6];
    const float* dec_Whh  = (const float*)d_in[7];
    const float* dec_bih  = (const float*)d_in[8];
    const float* dec_bhh  = (const float*)d_in[9];
    const float* attn_W   = (const float*)d_in[10];
    const float* attn_b   = (const float*)d_in[11];
    const float* out_W    = (const float*)d_in[12];
    const float* out_b    = (const float*)d_in[13];
    float* out = (float*)d_out;

    static int configured = 0;
    if (!configured) {
        cudaFuncSetAttribute(mega, cudaFuncAttributeMaxDynamicSharedMemorySize, 197632);
        configured = 1;
    }
    k_reset<<<1, 1>>>();
    mega<<<GRIDN, 256, 197632>>>(ing, emb, enc_Wih, enc_Whh, enc_bih, enc_bhh,
                                 dec_Wih, dec_Whh, dec_bih, dec_bhh,
                                 attn_W, attn_b, out_W, out_b, out);
}

// round 5
// speedup vs baseline: 1.5369x; 1.0064x over previous
#include <cuda_runtime.h>
#include <cuda_bf16.h>
#include <cstdint>

#define BB 32
#define SS 100
#define TT 100
#define EE 128
#define HH 256
#define VV 32000
#define G3 (3*HH)
#define TV (TT*VV)
#define GRIDN 148
#define BST 36      // logits h staging stride [k][b]
#define XST 649     // P1 x staging stride [b][k], gcd(9,32)=1 -> conflict-free
#define EST 193     // encoder weight smem stride [k][col], conflict-free

typedef unsigned long long ull;

// ---------------- device scratch ----------------
__device__ float g_Xih[BB*SS*G3];
__device__ float g_enc_outs[BB*SS*HH];
__device__ float g_enc_part[BB*SS];
__device__ float g_h[2][BB*HH];
__device__ float g_hx[BB*HH];            // encoder h exchange
__device__ float g_ctx[BB*HH];
__device__ ull g_amax[2][BB];
__device__ unsigned g_ctr;
__device__ unsigned g_ectr[BB];          // per-batch-group mini barrier
__device__ float g_oWT[(size_t)HH*VV];   // out_W transposed [k][v]
__device__ float g_eWihT[EE*G3];         // enc_Wih transposed [k][row]

// ---------------- helpers ----------------
__device__ __forceinline__ float sigf(float x) { return 1.0f / (1.0f + expf(-x)); }
__device__ __forceinline__ unsigned fkey(float f) {
    unsigned u = __float_as_uint(f);
    return (u & 0x80000000u) ? ~u : (u | 0x80000000u);
}
__device__ __forceinline__ ull pk2(float x, float y) {
    ull r; asm("mov.b64 %0, {%1, %2};" : "=l"(r) : "f"(x), "f"(y)); return r;
}
__device__ __forceinline__ void upk2(ull p, float &x, float &y) {
    asm("mov.b64 {%0, %1}, %2;" : "=f"(x), "=f"(y) : "l"(p));
}
__device__ __forceinline__ ull fma2(ull a, ull b, ull c) {
    ull d; asm("fma.rn.f32x2 %0, %1, %2, %3;" : "=l"(d) : "l"(a), "l"(b), "l"(c)); return d;
}

// grid barrier (monotonic counter)
__device__ __forceinline__ void gbar(int &nbar) {
    __syncthreads();
    if (threadIdx.x == 0) {
        __threadfence();
        unsigned tgt = (unsigned)(nbar + 1) * GRIDN;
        atomicAdd(&g_ctr, 1u);
        unsigned iter = 0;
        while (true) {
            unsigned v;
            asm volatile("ld.acquire.gpu.global.u32 %0, [%1];" : "=r"(v) : "l"(&g_ctr));
            if (v >= tgt) break;
            if (++iter > 8000000u) break;
            __nanosleep(64);
        }
        __threadfence();
    }
    nbar++;
    __syncthreads();
}

// 4-CTA mini barrier (encoder group), tight poll
__device__ __forceinline__ void minibar(int grp, int step) {
    __syncthreads();
    if (threadIdx.x == 0) {
        __threadfence();
        unsigned tgt = (unsigned)(step + 1) * 4u;
        atomicAdd(&g_ectr[grp], 1u);
        unsigned iter = 0;
        while (true) {
            unsigned v;
            asm volatile("ld.acquire.gpu.global.u32 %0, [%1];" : "=r"(v) : "l"(&g_ectr[grp]));
            if (v >= tgt) break;
            if (++iter > 20000000u) break;
        }
        __threadfence();
    }
    __syncthreads();
}

__global__ void k_reset() {
    g_ctr = 0u;
    for (int i = 0; i < BB; i++) g_ectr[i] = 0u;
}

__device__ __forceinline__ float rsum256(float v, float* red) {
    int tid = threadIdx.x;
    red[tid] = v; __syncthreads();
    #pragma unroll
    for (int o = 128; o > 0; o >>= 1) { if (tid < o) red[tid] += red[tid + o]; __syncthreads(); }
    float r = red[0]; __syncthreads();
    return r;
}
__device__ __forceinline__ float rmax256(float v, float* red) {
    int tid = threadIdx.x;
    red[tid] = v; __syncthreads();
    #pragma unroll
    for (int o = 128; o > 0; o >>= 1) { if (tid < o) red[tid] = fmaxf(red[tid], red[tid + o]); __syncthreads(); }
    float r = red[0]; __syncthreads();
    return r;
}

// ---------------- the megakernel ----------------
__global__ void __launch_bounds__(256, 1)
mega(const int* __restrict__ ing, const float* __restrict__ emb,
     const float* __restrict__ eWih, const float* __restrict__ eWhh,
     const float* __restrict__ ebih, const float* __restrict__ ebhh,
     const float* __restrict__ dWih, const float* __restrict__ dWhh,
     const float* __restrict__ dbih, const float* __restrict__ dbhh,
     const float* __restrict__ aW, const float* __restrict__ ab,
     const float* __restrict__ oW, const float* __restrict__ ob,
     float* __restrict__ out)
{
    extern __shared__ float dyn[];
    float* wsm = dyn;            // decoder: 3840-float weight slice / encoder: wTs[256][EST]
    float* buf = dyn + 3840;     // staging

    __shared__ float S[8][2][32];
    __shared__ float S4[4][3][64];
    __shared__ float hs[HH];
    __shared__ float ebs[192];
    __shared__ float red[256];
    __shared__ float ws[128];
    __shared__ int   toks[BB];
    __shared__ ull   slots[BB];

    const int c = blockIdx.x, tid = threadIdx.x;
    const int w = tid >> 5, lane = tid & 31;
    const int tx = tid & 31, ty = tid >> 5;
    int nbar = 0;

    // ============ Phase A: zero h0 + transposes (oW, eWih) ============
    if (c == 0) for (int i = tid; i < BB*HH; i += 256) g_h[0][i] = 0.0f;
    {
        float* tbuf = buf;   // 32x33
        for (int tile = c; tile < 8096; tile += GRIDN) {
            __syncthreads();
            if (tile < 8000) {
                int vt = tile >> 3, kt = tile & 7;
                int v0 = vt*32, k0 = kt*32;
                #pragma unroll
                for (int i = 0; i < 4; i++) {
                    int vv = ty + 8*i;
                    tbuf[vv*33 + tx] = oW[(size_t)(v0+vv)*HH + k0 + tx];
                }
                __syncthreads();
                #pragma unroll
                for (int i = 0; i < 4; i++) {
                    int kk = ty + 8*i;
                    g_oWT[(size_t)(k0+kk)*VV + v0 + tx] = tbuf[tx*33 + kk];
                }
            } else {
                int tt = tile - 8000;
                int rt = tt >> 2, kt = tt & 3;
                int r0 = rt*32, k0 = kt*32;
                #pragma unroll
                for (int i = 0; i < 4; i++) {
                    int rr = ty + 8*i;
                    tbuf[rr*33 + tx] = eWih[(size_t)(r0+rr)*EE + k0 + tx];
                }
                __syncthreads();
                #pragma unroll
                for (int i = 0; i < 4; i++) {
                    int kk = ty + 8*i;
                    g_eWihT[(k0+kk)*G3 + r0 + tx] = tbuf[tx*33 + kk];
                }
            }
        }
    }
    gbar(nbar);

    // ============ Phase B: Xih GEMM (c<100), then encoder weight slice (c<128) ============
    if (c < 100) {
        int p0 = c*32;
        if (tid < 32) toks[tid] = ing[p0 + tid];
        __syncthreads();
        for (int idx = tid; idx < EE*32; idx += 256) {
            int p = idx >> 7, k = idx & 127;
            buf[k*BST + p] = emb[(size_t)toks[p]*EE + k];
        }
        __syncthreads();
        ull acc[3][16];
        #pragma unroll
        for (int g = 0; g < 3; g++) {
            float bi = ebih[tid + g*256];
            ull bv = pk2(bi, bi);
            #pragma unroll
            for (int j = 0; j < 16; j++) acc[g][j] = bv;
        }
        #pragma unroll 2
        for (int k = 0; k < EE; k++) {
            float w0 = g_eWihT[k*G3 + tid];
            float w1 = g_eWihT[k*G3 + 256 + tid];
            float w2 = g_eWihT[k*G3 + 512 + tid];
            ull W0 = pk2(w0, w0), W1 = pk2(w1, w1), W2 = pk2(w2, w2);
            const ulonglong2* xp = (const ulonglong2*)(buf + k*BST);
            #pragma unroll
            for (int i = 0; i < 8; i++) {
                ulonglong2 hv = xp[i];
                acc[0][2*i]   = fma2(W0, hv.x, acc[0][2*i]);
                acc[0][2*i+1] = fma2(W0, hv.y, acc[0][2*i+1]);
                acc[1][2*i]   = fma2(W1, hv.x, acc[1][2*i]);
                acc[1][2*i+1] = fma2(W1, hv.y, acc[1][2*i+1]);
                acc[2][2*i]   = fma2(W2, hv.x, acc[2][2*i]);
                acc[2][2*i+1] = fma2(W2, hv.y, acc[2][2*i+1]);
            }
        }
        #pragma unroll
        for (int g = 0; g < 3; g++) {
            int r = tid + g*256;
            #pragma unroll
            for (int j = 0; j < 16; j++) {
                float f0, f1;
                upk2(acc[g][j], f0, f1);
                g_Xih[(size_t)(p0 + 2*j)*G3 + r] = f0;
                g_Xih[(size_t)(p0 + 2*j + 1)*G3 + r] = f1;
            }
        }
    }
    __syncthreads();
    if (c < 128) {
        // encoder weights: wTs[k*EST + col], col = g*64+jl, weight row = g*256 + part*64 + jl
        int part = c & 3;
        for (int idx = tid; idx < 192*64; idx += 256) {
            int k4 = idx & 63, r = idx >> 6;
            int g = r >> 6, jl = r & 63;
            float4 v = *(const float4*)(eWhh + (size_t)(g*256 + part*64 + jl)*HH + 4*k4);
            wsm[(4*k4+0)*EST + r] = v.x;
            wsm[(4*k4+1)*EST + r] = v.y;
            wsm[(4*k4+2)*EST + r] = v.z;
            wsm[(4*k4+3)*EST + r] = v.w;
        }
        // bias slice
        for (int i = tid; i < 192; i += 256) {
            int g = i >> 6, jl = i & 63;
            ebs[i] = ebhh[g*256 + part*64 + jl];
        }
        if (tid < HH) hs[tid] = 0.0f;
    }
    gbar(nbar);

    // ============ Encoder: 32 groups x 4 CTAs, mini-barriers only ============
    if (c < 128) {
        int b = c >> 2, part = c & 3;
        for (int s = 0; s < SS; s++) {
            // partials: thread (jl, q)
            int jl = tid & 63, q = tid >> 6;
            float aR = 0.f, aZ = 0.f, aN = 0.f;
            const float* wp = wsm + (q*64)*EST;
            #pragma unroll 4
            for (int kk = 0; kk < 64; kk++) {
                float hv = hs[q*64 + kk];
                aR += wp[kk*EST + jl] * hv;
                aZ += wp[kk*EST + 64 + jl] * hv;
                aN += wp[kk*EST + 128 + jl] * hv;
            }
            S4[q][0][jl] = aR; S4[q][1][jl] = aZ; S4[q][2][jl] = aN;
            __syncthreads();
            if (tid < 64) {
                int j = part*64 + tid;
                float rs = S4[0][0][tid]+S4[1][0][tid]+S4[2][0][tid]+S4[3][0][tid];
                float zs = S4[0][1][tid]+S4[1][1][tid]+S4[2][1][tid]+S4[3][1][tid];
                float ns = S4[0][2][tid]+S4[1][2][tid]+S4[2][2][tid]+S4[3][2][tid];
                const float* gi = g_Xih + ((size_t)b*SS + s)*G3;
                float r = sigf(gi[j] + rs + ebs[tid]);
                float z = sigf(gi[HH + j] + zs + ebs[64 + tid]);
                float n = tanhf(gi[2*HH + j] + r*(ns + ebs[128 + tid]));
                float h2 = (1.0f - z)*n + z*hs[j];
                g_enc_outs[((size_t)b*SS + s)*HH + j] = h2;
                g_hx[b*HH + j] = h2;
                if (s == SS-1) g_h[0][b*HH + j] = h2;
            }
            minibar(b, s);
            if (tid < HH) hs[tid] = g_hx[b*HH + tid];
            __syncthreads();
        }
    }
    gbar(nbar);

    // ============ enc_part + decoder weight slice ============
    if (c < 128) {
        int j0 = 2*c;
        for (int g = tid; g < 3840; g += 256) {
            int jl = (g >= 1920) ? 1 : 0;
            int gg = g - jl*1920;
            int j = j0 + jl;
            int rl, k;
            if (gg < 640)       { rl = 0; k = gg; }
            else if (gg < 1280) { rl = 1; k = gg - 640; }
            else if (gg < 1664) { rl = 2; k = gg - 1280; }
            else                { rl = 3; k = gg - 1664; }
            float v;
            if (rl == 0)      v = (k < 384) ? dWih[(size_t)j*384 + k]          : dWhh[(size_t)j*HH + (k-384)];
            else if (rl == 1) v = (k < 384) ? dWih[(size_t)(256+j)*384 + k]    : dWhh[(size_t)(256+j)*HH + (k-384)];
            else if (rl == 2) v = dWih[(size_t)(512+j)*384 + k];
            else              v = dWhh[(size_t)(512+j)*HH + k];
            wsm[g] = v;
        }
    }
    {
        int gt = c*256 + tid;
        if (gt < BB*SS) {
            const float4* e4 = (const float4*)(g_enc_outs + (size_t)gt*HH);
            const float4* w4 = (const float4*)aW;
            float a0 = ab[0], a1=0,a2=0,a3=0;
            #pragma unroll 8
            for (int k = 0; k < HH/4; k++) {
                float4 e = e4[k]; float4 ww = __ldg(&w4[k]);
                a0 += e.x*ww.x; a1 += e.y*ww.y; a2 += e.z*ww.z; a3 += e.w*ww.w;
            }
            g_enc_part[gt] = (a0+a1)+(a2+a3);
        }
    }
    gbar(nbar);

    // ============ decoder ============
    static const int rowoff_[8] = {0,640,1280,1664,1920,2560,3200,3584};
    static const int s0row_[8] = {0,0,1,2,4,4,5,6};
    static const int s0k_[8]   = {0,480,320,160,0,480,320,160};
    static const int s0len_[8] = {480,160,320,224,480,160,320,224};
    static const int s1row_[8] = {0,1,2,3,4,5,6,7};
    static const int s1len_[8] = {0,320,160,256,0,320,160,256};

    auto do_attn = [&](const float* h) {
        int i = c - 125;
        int nb = (i + 23 < BB) ? 2 : 1;
        for (int q = 0; q < nb; q++) {
            int b = i + q*23;
            float p = h[b*HH + tid] * aW[HH + tid];
            float hw = rsum256(p, red);
            float sc = (tid < SS) ? (g_enc_part[b*SS + tid] + hw) : -1e30f;
            float mx = rmax256(sc, red);
            float e = (tid < SS) ? expf(sc - mx) : 0.0f;
            if (tid < 128) ws[tid] = (tid < SS) ? e : 0.0f;
            float inv = 1.0f / rsum256(e, red);
            __syncthreads();
            int j = tid;
            const float* eo = g_enc_outs + (size_t)b*SS*HH + j;
            float a0=0, a1=0;
            #pragma unroll 4
            for (int s = 0; s < SS; s += 2) {
                a0 += ws[s] * eo[(size_t)s*HH];
                a1 += ws[s+1] * eo[(size_t)(s+1)*HH];
            }
            g_ctx[b*HH + j] = (a0 + a1) * inv;
            __syncthreads();
        }
    };

    if (c >= 125) do_attn(g_h[0]);
    gbar(nbar);

    for (int t = 0; t < TT; t++) {
        // -------- P1: GRU (c<128) --------
        if (c < 128) {
            if (tid < BB)
                toks[tid] = (t == 0) ? 1
                    : (int)(0xFFFFFFFFu - (unsigned)(g_amax[(t-1) & 1][tid] & 0xFFFFFFFFull));
            if (c == 0 && tid >= 32 && tid < 64) g_amax[t & 1][tid - 32] = 0ULL;
            __syncthreads();
            const float* hin = g_h[t & 1];
            // stage x = [emb, ctx, h] as [b][XST], coalesced loads, conflict-free stores
            {
                int b = tid >> 3, f = tid & 7;
                float* xr = buf + b*XST;
                #pragma unroll
                for (int i = 0; i < 4; i++) {
                    int k4 = f + 8*i;
                    float4 v = *(const float4*)(emb + (size_t)toks[b]*EE + 4*k4);
                    xr[4*k4+0]=v.x; xr[4*k4+1]=v.y; xr[4*k4+2]=v.z; xr[4*k4+3]=v.w;
                }
                #pragma unroll
                for (int i = 0; i < 8; i++) {
                    int k4 = f + 8*i;
                    float4 v = *(const float4*)(g_ctx + b*HH + 4*k4);
                    int o = 128 + 4*k4;
                    xr[o]=v.x; xr[o+1]=v.y; xr[o+2]=v.z; xr[o+3]=v.w;
                }
                #pragma unroll
                for (int i = 0; i < 8; i++) {
                    int k4 = f + 8*i;
                    float4 v = *(const float4*)(hin + b*HH + 4*k4);
                    int o = 384 + 4*k4;
                    xr[o]=v.x; xr[o+1]=v.y; xr[o+2]=v.z; xr[o+3]=v.w;
                }
            }
            __syncthreads();
            const float* xb = buf + lane*XST;
            {
                int r0 = s0row_[w], k0 = s0k_[w], l0 = s0len_[w];
                const float4* wv = (const float4*)(wsm + rowoff_[r0] + k0);
                int bo = (((r0 & 3) == 3) ? 384 : 0) + k0;
                float a0=0,a1=0,a2=0,a3=0;
                #pragma unroll 4
                for (int i = 0; i < l0/4; i++) {
                    float4 x = wv[i];
                    const float* xp = xb + bo + 4*i;
                    a0 += x.x*xp[0]; a1 += x.y*xp[1];
                    a2 += x.z*xp[2]; a3 += x.w*xp[3];
                }
                S[w][0][lane] = (a0+a1)+(a2+a3);
            }
            {
                int r1 = s1row_[w], l1 = s1len_[w];
                float acc = 0.0f;
                if (l1 > 0) {
                    const float4* wv = (const float4*)(wsm + rowoff_[r1]);
                    int bo = ((r1 & 3) == 3) ? 384 : 0;
                    float a0=0,a1=0,a2=0,a3=0;
                    #pragma unroll 4
                    for (int i = 0; i < l1/4; i++) {
                        float4 x = wv[i];
                        const float* xp = xb + bo + 4*i;
                        a0 += x.x*xp[0]; a1 += x.y*xp[1];
                        a2 += x.z*xp[2]; a3 += x.w*xp[3];
                    }
                    acc = (a0+a1)+(a2+a3);
                }
                S[w][1][lane] = acc;
            }
            __syncthreads();
            if (w == 0 || w == 4) {
                int jl = w >> 2, base = jl*4;
                int j = 2*c + jl, b = lane;
                float r_in = S[base+0][0][b] + S[base+1][0][b];
                float z_in = S[base+1][1][b] + S[base+2][0][b];
                float nx   = S[base+2][1][b] + S[base+3][0][b];
                float nh   = S[base+3][1][b];
                float r = sigf(r_in + dbih[j] + dbhh[j]);
                float z = sigf(z_in + dbih[HH + j] + dbhh[HH + j]);
                float n = tanhf(nx + dbih[2*HH + j] + r*(nh + dbhh[2*HH + j]));
                float hprev = buf[b*XST + 384 + j];
                float h2 = (1.0f - z)*n + z*hprev;
                g_h[(t+1) & 1][b*HH + j] = h2;
            }
        }
        gbar(nbar);

        // -------- P2: logits+argmax (c<125) || attn t+1 (c>=125) --------
        if (c < 125) {
            const float* h = g_h[(t+1) & 1];
            if (tid < BB) slots[tid] = 0ULL;
            for (int idx = tid; idx < BB*HH; idx += 256)
                buf[(idx & (HH-1))*BST + (idx >> 8)] = h[idx];
            __syncthreads();

            int v = c*256 + tid;
            float bias = ob[v];
            ull acc[16];
            ull binit = pk2(bias, bias);
            #pragma unroll
            for (int i = 0; i < 16; i++) acc[i] = binit;

            const float* wp = g_oWT + v;
            float wreg[8];
            #pragma unroll
            for (int i = 0; i < 8; i++) wreg[i] = wp[(size_t)i*VV];

            for (int k8 = 0; k8 < 32; k8++) {
                float wnext[8];
                if (k8 < 31) {
                    #pragma unroll
                    for (int i = 0; i < 8; i++) wnext[i] = wp[(size_t)(k8*8 + 8 + i)*VV];
                }
                #pragma unroll
                for (int i = 0; i < 8; i++) {
                    int k = k8*8 + i;
                    ull W = pk2(wreg[i], wreg[i]);
                    const ulonglong2* hp = (const ulonglong2*)(buf + k*BST);
                    #pragma unroll
                    for (int jj = 0; jj < 8; jj++) {
                        ulonglong2 hv = hp[jj];
                        acc[2*jj]   = fma2(W, hv.x, acc[2*jj]);
                        acc[2*jj+1] = fma2(W, hv.y, acc[2*jj+1]);
                    }
                }
                if (k8 < 31) {
                    #pragma unroll
                    for (int i = 0; i < 8; i++) wreg[i] = wnext[i];
                }
            }

            float* outp = out + (size_t)t*VV;
            #pragma unroll
            for (int m = 0; m < 16; m++) {
                float f0, f1;
                upk2(acc[m], f0, f1);
                outp[(size_t)(2*m)*TV + v]   = f0;
                outp[(size_t)(2*m+1)*TV + v] = f1;
                {
                    unsigned key = fkey(f0);
                    unsigned wm = __reduce_max_sync(0xffffffffu, key);
                    unsigned mk = __ballot_sync(0xffffffffu, key == wm);
                    if (lane == (__ffs(mk) - 1))
                        atomicMax(&slots[2*m], ((ull)wm << 32) | (ull)(0xFFFFFFFFu - (unsigned)v));
                }
                {
                    unsigned key = fkey(f1);
                    unsigned wm = __reduce_max_sync(0xffffffffu, key);
                    unsigned mk = __ballot_sync(0xffffffffu, key == wm);
                    if (lane == (__ffs(mk) - 1))
                        atomicMax(&slots[2*m+1], ((ull)wm << 32) | (ull)(0xFFFFFFFFu - (unsigned)v));
                }
            }
            __syncthreads();
            if (tid < BB) atomicMax(&g_amax[t & 1][tid], slots[tid]);
        } else if (t < TT-1) {
            do_attn(g_h[(t+1) & 1]);
        }
        gbar(nbar);
    }
}

// ---------------- host launch ----------------
extern "C" void kernel_launch(void* const* d_in, const int* in_sizes, int n_in,
                              void* d_out, int out_size) {
    const int*   ing      = (const int*)d_in[0];
    const float* emb      = (const float*)d_in[1];
    const float* enc_Wih  = (const float*)d_in[2];
    const float* enc_Whh  = (const float*)d_in[3];
    const float* enc_bih  = (const float*)d_in[4];
    const float* enc_bhh  = (const float*)d_in[5];
    const float* dec_Wih  = (const float*)d_in[6];
    const float* dec_Whh  = (const float*)d_in[7];
    const float* dec_bih  = (const float*)d_in[8];
    const float* dec_bhh  = (const float*)d_in[9];
    const float* attn_W   = (const float*)d_in[10];
    const float* attn_b   = (const float*)d_in[11];
    const float* out_W    = (const float*)d_in[12];
    const float* out_b    = (const float*)d_in[13];
    float* out = (float*)d_out;

    static int configured = 0;
    if (!configured) {
        cudaFuncSetAttribute(mega, cudaFuncAttributeMaxDynamicSharedMemorySize, 197632);
        configured = 1;
    }
    k_reset<<<1, 1>>>();
    mega<<<GRIDN, 256, 197632>>>(ing, emb, enc_Wih, enc_Whh, enc_bih, enc_bhh,
                                 dec_Wih, dec_Whh, dec_bih, dec_bhh,
                                 attn_W, attn_b, out_W, out_b, out);
}

// round 6
// speedup vs baseline: 1.7888x; 1.1639x over previous
#include <cuda_runtime.h>
#include <cuda_bf16.h>
#include <cstdint>

#define BB 32
#define SS 100
#define TT 100
#define EE 128
#define HH 256
#define VV 32000
#define G3 (3*HH)
#define TV (TT*VV)
#define GRIDN 148
#define BST 36      // logits h staging stride [k][b]
#define XST 649     // P1 x staging stride [b][k], gcd(9,32)=1 -> conflict-free
#define EST 193     // encoder weight smem stride [k][col], conflict-free

typedef unsigned long long ull;

// ---------------- device scratch ----------------
__device__ float g_Xih[BB*SS*G3];
__device__ float g_enc_outs[BB*SS*HH];
__device__ float g_enc_part[BB*SS];
__device__ float g_h[2][BB*HH];
__device__ float g_hx[BB*HH];            // encoder h exchange
__device__ float g_ctx[BB*HH];
__device__ ull g_amax[2][BB];
__device__ unsigned g_ctr;
__device__ unsigned g_ectr[BB];          // per-batch-group mini barrier
__device__ float g_oWT[(size_t)HH*VV];   // out_W transposed [k][v]
__device__ float g_eWihT[EE*G3];         // enc_Wih transposed [k][row]

// ---------------- helpers ----------------
__device__ __forceinline__ float sigf(float x) { return 1.0f / (1.0f + expf(-x)); }
__device__ __forceinline__ unsigned fkey(float f) {
    unsigned u = __float_as_uint(f);
    return (u & 0x80000000u) ? ~u : (u | 0x80000000u);
}
__device__ __forceinline__ ull pk2(float x, float y) {
    ull r; asm("mov.b64 %0, {%1, %2};" : "=l"(r) : "f"(x), "f"(y)); return r;
}
__device__ __forceinline__ void upk2(ull p, float &x, float &y) {
    asm("mov.b64 {%0, %1}, %2;" : "=f"(x), "=f"(y) : "l"(p));
}
__device__ __forceinline__ ull fma2(ull a, ull b, ull c) {
    ull d; asm("fma.rn.f32x2 %0, %1, %2, %3;" : "=l"(d) : "l"(a), "l"(b), "l"(c)); return d;
}

// grid barrier (monotonic counter)
__device__ __forceinline__ void gbar(int &nbar) {
    __syncthreads();
    if (threadIdx.x == 0) {
        __threadfence();
        unsigned tgt = (unsigned)(nbar + 1) * GRIDN;
        atomicAdd(&g_ctr, 1u);
        unsigned iter = 0;
        while (true) {
            unsigned v;
            asm volatile("ld.acquire.gpu.global.u32 %0, [%1];" : "=r"(v) : "l"(&g_ctr));
            if (v >= tgt) break;
            if (++iter > 8000000u) break;
            __nanosleep(64);
        }
        __threadfence();
    }
    nbar++;
    __syncthreads();
}

// 4-CTA mini barrier (encoder group), tight poll
__device__ __forceinline__ void minibar(int grp, int step) {
    __syncthreads();
    if (threadIdx.x == 0) {
        __threadfence();
        unsigned tgt = (unsigned)(step + 1) * 4u;
        atomicAdd(&g_ectr[grp], 1u);
        unsigned iter = 0;
        while (true) {
            unsigned v;
            asm volatile("ld.acquire.gpu.global.u32 %0, [%1];" : "=r"(v) : "l"(&g_ectr[grp]));
            if (v >= tgt) break;
            if (++iter > 20000000u) break;
        }
        __threadfence();
    }
    __syncthreads();
}

__global__ void k_reset() {
    g_ctr = 0u;
    for (int i = 0; i < BB; i++) g_ectr[i] = 0u;
}

__device__ __forceinline__ float rsum256(float v, float* red) {
    int tid = threadIdx.x;
    red[tid] = v; __syncthreads();
    #pragma unroll
    for (int o = 128; o > 0; o >>= 1) { if (tid < o) red[tid] += red[tid + o]; __syncthreads(); }
    float r = red[0]; __syncthreads();
    return r;
}
__device__ __forceinline__ float rmax256(float v, float* red) {
    int tid = threadIdx.x;
    red[tid] = v; __syncthreads();
    #pragma unroll
    for (int o = 128; o > 0; o >>= 1) { if (tid < o) red[tid] = fmaxf(red[tid], red[tid + o]); __syncthreads(); }
    float r = red[0]; __syncthreads();
    return r;
}

// ---------------- the megakernel ----------------
__global__ void __launch_bounds__(256, 1)
mega(const int* __restrict__ ing, const float* __restrict__ emb,
     const float* __restrict__ eWih, const float* __restrict__ eWhh,
     const float* __restrict__ ebih, const float* __restrict__ ebhh,
     const float* __restrict__ dWih, const float* __restrict__ dWhh,
     const float* __restrict__ dbih, const float* __restrict__ dbhh,
     const float* __restrict__ aW, const float* __restrict__ ab,
     const float* __restrict__ oW, const float* __restrict__ ob,
     float* __restrict__ out)
{
    extern __shared__ float dyn[];
    float* wsm = dyn;            // decoder: 3840-float weight slice / encoder: wTs[256][EST]
    float* buf = dyn + 3840;     // staging

    __shared__ float S[8][2][32];
    __shared__ float S4[4][3][64];
    __shared__ float hs[HH];
    __shared__ float ebs[192];
    __shared__ float red[256];
    __shared__ float ws[128];
    __shared__ int   toks[BB];
    __shared__ ull   slots[BB];

    const int c = blockIdx.x, tid = threadIdx.x;
    const int w = tid >> 5, lane = tid & 31;
    const int tx = tid & 31, ty = tid >> 5;
    int nbar = 0;

    // ============ Phase A: zero h0 + transposes (oW, eWih) ============
    if (c == 0) for (int i = tid; i < BB*HH; i += 256) g_h[0][i] = 0.0f;
    {
        float* tbuf = buf;   // 32x33
        for (int tile = c; tile < 8096; tile += GRIDN) {
            __syncthreads();
            if (tile < 8000) {
                int vt = tile >> 3, kt = tile & 7;
                int v0 = vt*32, k0 = kt*32;
                #pragma unroll
                for (int i = 0; i < 4; i++) {
                    int vv = ty + 8*i;
                    tbuf[vv*33 + tx] = oW[(size_t)(v0+vv)*HH + k0 + tx];
                }
                __syncthreads();
                #pragma unroll
                for (int i = 0; i < 4; i++) {
                    int kk = ty + 8*i;
                    g_oWT[(size_t)(k0+kk)*VV + v0 + tx] = tbuf[tx*33 + kk];
                }
            } else {
                int tt = tile - 8000;
                int rt = tt >> 2, kt = tt & 3;
                int r0 = rt*32, k0 = kt*32;
                #pragma unroll
                for (int i = 0; i < 4; i++) {
                    int rr = ty + 8*i;
                    tbuf[rr*33 + tx] = eWih[(size_t)(r0+rr)*EE + k0 + tx];
                }
                __syncthreads();
                #pragma unroll
                for (int i = 0; i < 4; i++) {
                    int kk = ty + 8*i;
                    g_eWihT[(k0+kk)*G3 + r0 + tx] = tbuf[tx*33 + kk];
                }
            }
        }
    }
    gbar(nbar);

    // ============ Phase B: Xih GEMM (c<100), then encoder weight slice (c<128) ============
    if (c < 100) {
        int p0 = c*32;
        if (tid < 32) toks[tid] = ing[p0 + tid];
        __syncthreads();
        for (int idx = tid; idx < EE*32; idx += 256) {
            int p = idx >> 7, k = idx & 127;
            buf[k*BST + p] = emb[(size_t)toks[p]*EE + k];
        }
        __syncthreads();
        ull acc[3][16];
        #pragma unroll
        for (int g = 0; g < 3; g++) {
            float bi = ebih[tid + g*256];
            ull bv = pk2(bi, bi);
            #pragma unroll
            for (int j = 0; j < 16; j++) acc[g][j] = bv;
        }
        #pragma unroll 2
        for (int k = 0; k < EE; k++) {
            float w0 = g_eWihT[k*G3 + tid];
            float w1 = g_eWihT[k*G3 + 256 + tid];
            float w2 = g_eWihT[k*G3 + 512 + tid];
            ull W0 = pk2(w0, w0), W1 = pk2(w1, w1), W2 = pk2(w2, w2);
            const ulonglong2* xp = (const ulonglong2*)(buf + k*BST);
            #pragma unroll
            for (int i = 0; i < 8; i++) {
                ulonglong2 hv = xp[i];
                acc[0][2*i]   = fma2(W0, hv.x, acc[0][2*i]);
                acc[0][2*i+1] = fma2(W0, hv.y, acc[0][2*i+1]);
                acc[1][2*i]   = fma2(W1, hv.x, acc[1][2*i]);
                acc[1][2*i+1] = fma2(W1, hv.y, acc[1][2*i+1]);
                acc[2][2*i]   = fma2(W2, hv.x, acc[2][2*i]);
                acc[2][2*i+1] = fma2(W2, hv.y, acc[2][2*i+1]);
            }
        }
        #pragma unroll
        for (int g = 0; g < 3; g++) {
            int r = tid + g*256;
            #pragma unroll
            for (int j = 0; j < 16; j++) {
                float f0, f1;
                upk2(acc[g][j], f0, f1);
                g_Xih[(size_t)(p0 + 2*j)*G3 + r] = f0;
                g_Xih[(size_t)(p0 + 2*j + 1)*G3 + r] = f1;
            }
        }
    }
    __syncthreads();
    if (c < 128) {
        int part = c & 3;
        for (int idx = tid; idx < 192*64; idx += 256) {
            int k4 = idx & 63, r = idx >> 6;
            int g = r >> 6, jl = r & 63;
            float4 v = *(const float4*)(eWhh + (size_t)(g*256 + part*64 + jl)*HH + 4*k4);
            wsm[(4*k4+0)*EST + r] = v.x;
            wsm[(4*k4+1)*EST + r] = v.y;
            wsm[(4*k4+2)*EST + r] = v.z;
            wsm[(4*k4+3)*EST + r] = v.w;
        }
        for (int i = tid; i < 192; i += 256) {
            int g = i >> 6, jl = i & 63;
            ebs[i] = ebhh[g*256 + part*64 + jl];
        }
        if (tid < HH) hs[tid] = 0.0f;
    }
    gbar(nbar);

    // ============ Encoder: 32 groups x 4 CTAs, mini-barriers only ============
    if (c < 128) {
        int b = c >> 2, part = c & 3;
        for (int s = 0; s < SS; s++) {
            int jl = tid & 63, q = tid >> 6;
            float aR = 0.f, aZ = 0.f, aN = 0.f;
            const float* wp = wsm + (q*64)*EST;
            #pragma unroll 4
            for (int kk = 0; kk < 64; kk++) {
                float hv = hs[q*64 + kk];
                aR += wp[kk*EST + jl] * hv;
                aZ += wp[kk*EST + 64 + jl] * hv;
                aN += wp[kk*EST + 128 + jl] * hv;
            }
            S4[q][0][jl] = aR; S4[q][1][jl] = aZ; S4[q][2][jl] = aN;
            __syncthreads();
            if (tid < 64) {
                int j = part*64 + tid;
                float rs = S4[0][0][tid]+S4[1][0][tid]+S4[2][0][tid]+S4[3][0][tid];
                float zs = S4[0][1][tid]+S4[1][1][tid]+S4[2][1][tid]+S4[3][1][tid];
                float ns = S4[0][2][tid]+S4[1][2][tid]+S4[2][2][tid]+S4[3][2][tid];
                const float* gi = g_Xih + ((size_t)b*SS + s)*G3;
                float r = sigf(gi[j] + rs + ebs[tid]);
                float z = sigf(gi[HH + j] + zs + ebs[64 + tid]);
                float n = tanhf(gi[2*HH + j] + r*(ns + ebs[128 + tid]));
                float h2 = (1.0f - z)*n + z*hs[j];
                g_enc_outs[((size_t)b*SS + s)*HH + j] = h2;
                g_hx[b*HH + j] = h2;
                if (s == SS-1) g_h[0][b*HH + j] = h2;
            }
            minibar(b, s);
            if (tid < HH) hs[tid] = g_hx[b*HH + tid];
            __syncthreads();
        }
    }
    gbar(nbar);

    // ============ enc_part + decoder weight slice ============
    if (c < 128) {
        int j0 = 2*c;
        for (int g = tid; g < 3840; g += 256) {
            int jl = (g >= 1920) ? 1 : 0;
            int gg = g - jl*1920;
            int j = j0 + jl;
            int rl, k;
            if (gg < 640)       { rl = 0; k = gg; }
            else if (gg < 1280) { rl = 1; k = gg - 640; }
            else if (gg < 1664) { rl = 2; k = gg - 1280; }
            else                { rl = 3; k = gg - 1664; }
            float v;
            if (rl == 0)      v = (k < 384) ? dWih[(size_t)j*384 + k]          : dWhh[(size_t)j*HH + (k-384)];
            else if (rl == 1) v = (k < 384) ? dWih[(size_t)(256+j)*384 + k]    : dWhh[(size_t)(256+j)*HH + (k-384)];
            else if (rl == 2) v = dWih[(size_t)(512+j)*384 + k];
            else              v = dWhh[(size_t)(512+j)*HH + k];
            wsm[g] = v;
        }
    }
    {
        int gt = c*256 + tid;
        if (gt < BB*SS) {
            const float4* e4 = (const float4*)(g_enc_outs + (size_t)gt*HH);
            const float4* w4 = (const float4*)aW;
            float a0 = ab[0], a1=0,a2=0,a3=0;
            #pragma unroll 8
            for (int k = 0; k < HH/4; k++) {
                float4 e = e4[k]; float4 ww = __ldg(&w4[k]);
                a0 += e.x*ww.x; a1 += e.y*ww.y; a2 += e.z*ww.z; a3 += e.w*ww.w;
            }
            g_enc_part[gt] = (a0+a1)+(a2+a3);
        }
    }
    gbar(nbar);

    // ============ decoder ============
    static const int rowoff_[8] = {0,640,1280,1664,1920,2560,3200,3584};
    static const int s0row_[8] = {0,0,1,2,4,4,5,6};
    static const int s0k_[8]   = {0,480,320,160,0,480,320,160};
    static const int s0len_[8] = {480,160,320,224,480,160,320,224};
    static const int s1row_[8] = {0,1,2,3,4,5,6,7};
    static const int s1len_[8] = {0,320,160,256,0,320,160,256};

    auto do_attn = [&](const float* h) {
        int i = c - 125;
        int nb = (i + 23 < BB) ? 2 : 1;
        for (int q = 0; q < nb; q++) {
            int b = i + q*23;
            float p = h[b*HH + tid] * aW[HH + tid];
            float hw = rsum256(p, red);
            float sc = (tid < SS) ? (g_enc_part[b*SS + tid] + hw) : -1e30f;
            float mx = rmax256(sc, red);
            float e = (tid < SS) ? expf(sc - mx) : 0.0f;
            if (tid < 128) ws[tid] = (tid < SS) ? e : 0.0f;
            float inv = 1.0f / rsum256(e, red);
            __syncthreads();
            int j = tid;
            const float* eo = g_enc_outs + (size_t)b*SS*HH + j;
            float a0=0, a1=0;
            #pragma unroll 4
            for (int s = 0; s < SS; s += 2) {
                a0 += ws[s] * eo[(size_t)s*HH];
                a1 += ws[s+1] * eo[(size_t)(s+1)*HH];
            }
            g_ctx[b*HH + j] = (a0 + a1) * inv;
            __syncthreads();
        }
    };

    if (c >= 125) do_attn(g_h[0]);
    gbar(nbar);

    for (int t = 0; t < TT; t++) {
        // -------- P1: GRU (c<128) --------
        if (c < 128) {
            if (tid < BB)
                toks[tid] = (t == 0) ? 1
                    : (int)(0xFFFFFFFFu - (unsigned)(g_amax[(t-1) & 1][tid] & 0xFFFFFFFFull));
            if (c == 0 && tid >= 32 && tid < 64) g_amax[t & 1][tid - 32] = 0ULL;
            __syncthreads();
            const float* hin = g_h[t & 1];
            {
                int b = tid >> 3, f = tid & 7;
                float* xr = buf + b*XST;
                #pragma unroll
                for (int i = 0; i < 4; i++) {
                    int k4 = f + 8*i;
                    float4 v = *(const float4*)(emb + (size_t)toks[b]*EE + 4*k4);
                    xr[4*k4+0]=v.x; xr[4*k4+1]=v.y; xr[4*k4+2]=v.z; xr[4*k4+3]=v.w;
                }
                #pragma unroll
                for (int i = 0; i < 8; i++) {
                    int k4 = f + 8*i;
                    float4 v = *(const float4*)(g_ctx + b*HH + 4*k4);
                    int o = 128 + 4*k4;
                    xr[o]=v.x; xr[o+1]=v.y; xr[o+2]=v.z; xr[o+3]=v.w;
                }
                #pragma unroll
                for (int i = 0; i < 8; i++) {
                    int k4 = f + 8*i;
                    float4 v = *(const float4*)(hin + b*HH + 4*k4);
                    int o = 384 + 4*k4;
                    xr[o]=v.x; xr[o+1]=v.y; xr[o+2]=v.z; xr[o+3]=v.w;
                }
            }
            __syncthreads();
            const float* xb = buf + lane*XST;
            {
                int r0 = s0row_[w], k0 = s0k_[w], l0 = s0len_[w];
                const float4* wv = (const float4*)(wsm + rowoff_[r0] + k0);
                int bo = (((r0 & 3) == 3) ? 384 : 0) + k0;
                float a0=0,a1=0,a2=0,a3=0;
                #pragma unroll 4
                for (int i = 0; i < l0/4; i++) {
                    float4 x = wv[i];
                    const float* xp = xb + bo + 4*i;
                    a0 += x.x*xp[0]; a1 += x.y*xp[1];
                    a2 += x.z*xp[2]; a3 += x.w*xp[3];
                }
                S[w][0][lane] = (a0+a1)+(a2+a3);
            }
            {
                int r1 = s1row_[w], l1 = s1len_[w];
                float acc = 0.0f;
                if (l1 > 0) {
                    const float4* wv = (const float4*)(wsm + rowoff_[r1]);
                    int bo = ((r1 & 3) == 3) ? 384 : 0;
                    float a0=0,a1=0,a2=0,a3=0;
                    #pragma unroll 4
                    for (int i = 0; i < l1/4; i++) {
                        float4 x = wv[i];
                        const float* xp = xb + bo + 4*i;
                        a0 += x.x*xp[0]; a1 += x.y*xp[1];
                        a2 += x.z*xp[2]; a3 += x.w*xp[3];
                    }
                    acc = (a0+a1)+(a2+a3);
                }
                S[w][1][lane] = acc;
            }
            __syncthreads();
            if (w == 0 || w == 4) {
                int jl = w >> 2, base = jl*4;
                int j = 2*c + jl, b = lane;
                float r_in = S[base+0][0][b] + S[base+1][0][b];
                float z_in = S[base+1][1][b] + S[base+2][0][b];
                float nx   = S[base+2][1][b] + S[base+3][0][b];
                float nh   = S[base+3][1][b];
                float r = sigf(r_in + dbih[j] + dbhh[j]);
                float z = sigf(z_in + dbih[HH + j] + dbhh[HH + j]);
                float n = tanhf(nx + dbih[2*HH + j] + r*(nh + dbhh[2*HH + j]));
                float hprev = buf[b*XST + 384 + j];
                float h2 = (1.0f - z)*n + z*hprev;
                g_h[(t+1) & 1][b*HH + j] = h2;
            }
        }
        gbar(nbar);

        // -------- P2: logits+argmax (c<125, 32v x 32b register tile) || attn (c>=125) --------
        if (c < 125) {
            const float* h = g_h[(t+1) & 1];
            if (tid < BB) slots[tid] = 0ULL;
            for (int idx = tid; idx < BB*HH; idx += 256)
                buf[(idx & (HH-1))*BST + (idx >> 8)] = h[idx];
            __syncthreads();

            const int vi = lane >> 2, bi = lane & 3;
            const int vlane = c*256 + w*32 + vi*4;
            float4 b4 = *(const float4*)(ob + vlane);
            ull acc[4][4];
            acc[0][0]=acc[0][1]=acc[0][2]=acc[0][3]=pk2(b4.x, b4.x);
            acc[1][0]=acc[1][1]=acc[1][2]=acc[1][3]=pk2(b4.y, b4.y);
            acc[2][0]=acc[2][1]=acc[2][2]=acc[2][3]=pk2(b4.z, b4.z);
            acc[3][0]=acc[3][1]=acc[3][2]=acc[3][3]=pk2(b4.w, b4.w);

            const float* wp = g_oWT + vlane;
            float4 wreg[8];
            #pragma unroll
            for (int i = 0; i < 8; i++) wreg[i] = *(const float4*)(wp + (size_t)i*VV);

            for (int k8 = 0; k8 < 32; k8++) {
                float4 wnext[8];
                if (k8 < 31) {
                    #pragma unroll
                    for (int i = 0; i < 8; i++)
                        wnext[i] = *(const float4*)(wp + (size_t)(k8*8 + 8 + i)*VV);
                }
                #pragma unroll
                for (int i = 0; i < 8; i++) {
                    int k = k8*8 + i;
                    const ulonglong2* hp = (const ulonglong2*)(buf + k*BST + bi*8);
                    ulonglong2 h01 = hp[0];   // b pairs (0,1),(2,3) of this bi group
                    ulonglong2 h23 = hp[1];   // b pairs (4,5),(6,7)
                    ull W;
                    W = pk2(wreg[i].x, wreg[i].x);
                    acc[0][0]=fma2(W,h01.x,acc[0][0]); acc[0][1]=fma2(W,h01.y,acc[0][1]);
                    acc[0][2]=fma2(W,h23.x,acc[0][2]); acc[0][3]=fma2(W,h23.y,acc[0][3]);
                    W = pk2(wreg[i].y, wreg[i].y);
                    acc[1][0]=fma2(W,h01.x,acc[1][0]); acc[1][1]=fma2(W,h01.y,acc[1][1]);
                    acc[1][2]=fma2(W,h23.x,acc[1][2]); acc[1][3]=fma2(W,h23.y,acc[1][3]);
                    W = pk2(wreg[i].z, wreg[i].z);
                    acc[2][0]=fma2(W,h01.x,acc[2][0]); acc[2][1]=fma2(W,h01.y,acc[2][1]);
                    acc[2][2]=fma2(W,h23.x,acc[2][2]); acc[2][3]=fma2(W,h23.y,acc[2][3]);
                    W = pk2(wreg[i].w, wreg[i].w);
                    acc[3][0]=fma2(W,h01.x,acc[3][0]); acc[3][1]=fma2(W,h01.y,acc[3][1]);
                    acc[3][2]=fma2(W,h23.x,acc[3][2]); acc[3][3]=fma2(W,h23.y,acc[3][3]);
                }
                if (k8 < 31) {
                    #pragma unroll
                    for (int i = 0; i < 8; i++) wreg[i] = wnext[i];
                }
            }

            // unpack: f[v][j], j = local b index 0..7 (b = bi*8 + j)
            float f[4][8];
            #pragma unroll
            for (int v = 0; v < 4; v++) {
                #pragma unroll
                for (int bp = 0; bp < 4; bp++)
                    upk2(acc[v][bp], f[v][2*bp], f[v][2*bp+1]);
            }
            float* outp = out + (size_t)t*VV;
            #pragma unroll
            for (int j = 0; j < 8; j++) {
                int b = bi*8 + j;
                *(float4*)(outp + (size_t)b*TV + vlane) =
                    make_float4(f[0][j], f[1][j], f[2][j], f[3][j]);
                // local argmax over 4 v
                unsigned bk = fkey(f[0][j]); unsigned bv = (unsigned)vlane;
                #pragma unroll
                for (int v = 1; v < 4; v++) {
                    unsigned kk = fkey(f[v][j]);
                    if (kk > bk) { bk = kk; bv = (unsigned)(vlane + v); }
                }
                ull kv = ((ull)bk << 32) | (ull)(0xFFFFFFFFu - bv);
                #pragma unroll
                for (int o = 4; o < 32; o <<= 1) {
                    ull other = __shfl_xor_sync(0xffffffffu, kv, o);
                    if (other > kv) kv = other;
                }
                if (vi == 0) atomicMax(&slots[b], kv);
            }
            __syncthreads();
            if (tid < BB) atomicMax(&g_amax[t & 1][tid], slots[tid]);
        } else if (t < TT-1) {
            do_attn(g_h[(t+1) & 1]);
        }
        gbar(nbar);
    }
}

// ---------------- host launch ----------------
extern "C" void kernel_launch(void* const* d_in, const int* in_sizes, int n_in,
                              void* d_out, int out_size) {
    const int*   ing      = (const int*)d_in[0];
    const float* emb      = (const float*)d_in[1];
    const float* enc_Wih  = (const float*)d_in[2];
    const float* enc_Whh  = (const float*)d_in[3];
    const float* enc_bih  = (const float*)d_in[4];
    const float* enc_bhh  = (const float*)d_in[5];
    const float* dec_Wih  = (const float*)d_in[6];
    const float* dec_Whh  = (const float*)d_in[7];
    const float* dec_bih  = (const float*)d_in[8];
    const float* dec_bhh  = (const float*)d_in[9];
    const float* attn_W   = (const float*)d_in[10];
    const float* attn_b   = (const float*)d_in[11];
    const float* out_W    = (const float*)d_in[12];
    const float* out_b    = (const float*)d_in[13];
    float* out = (float*)d_out;

    static int configured = 0;
    if (!configured) {
        cudaFuncSetAttribute(mega, cudaFuncAttributeMaxDynamicSharedMemorySize, 197632);
        configured = 1;
    }
    k_reset<<<1, 1>>>();
    mega<<<GRIDN, 256, 197632>>>(ing, emb, enc_Wih, enc_Whh, enc_bih, enc_bhh,
                                 dec_Wih, dec_Whh, dec_bih, dec_bhh,
                                 attn_W, attn_b, out_W, out_b, out);
}